// round 3
// baseline (speedup 1.0000x reference)
#include <cuda_runtime.h>
#include <math.h>

// Problem constants
#define B_    16
#define CIN   512
#define T_    4096
#define E_    256
#define NC    1024
#define NTOK  (B_ * T_)          // 65536
#define NGATH 2048               // gather blocks (32 tokens each)

// ---------------------------------------------------------------------------
// Scratch (static __device__ arrays — no runtime allocation)
// ---------------------------------------------------------------------------
__device__ float              g_x[(size_t)NTOK * E_];   // 64 MiB projected features [n][e]
__device__ unsigned long long g_minpack[NTOK];          // packed (dist_bits<<32 | idx)
__device__ int                g_count[NC];
__device__ float              g_enorm[NC];
__device__ float              g_losspart[NGATH];

// ---------------------------------------------------------------------------
// Init: minpack -> +inf, counts -> 0
// ---------------------------------------------------------------------------
__global__ void init_k() {
    int i = blockIdx.x * blockDim.x + threadIdx.x;
    if (i < NTOK) g_minpack[i] = 0xFFFFFFFFFFFFFFFFull;
    if (i < NC)   g_count[i]   = 0;
}

// ---------------------------------------------------------------------------
// Codebook row norms: one warp per row
// ---------------------------------------------------------------------------
__global__ void enorm_k(const float* __restrict__ embed) {
    int warp = (blockIdx.x * blockDim.x + threadIdx.x) >> 5;
    int lane = threadIdx.x & 31;
    if (warp >= NC) return;
    const float* row = embed + (size_t)warp * E_;
    float s = 0.f;
    #pragma unroll
    for (int e = lane; e < E_; e += 32) { float v = row[e]; s += v * v; }
    #pragma unroll
    for (int o = 16; o; o >>= 1) s += __shfl_down_sync(0xffffffffu, s, o);
    if (lane == 0) g_enorm[warp] = s;
}

// ---------------------------------------------------------------------------
// GEMM A: x[n][e] = sum_c in[b][c][t] * W[e][c] + bias[e]
// Tile 128(t) x 128(e), BK=16, 256 threads, 8x8 microtile.
// ---------------------------------------------------------------------------
__global__ __launch_bounds__(256) void gemmA_k(const float* __restrict__ A_all,
                                               const float* __restrict__ W,
                                               const float* __restrict__ bias) {
    __shared__ float sA[16][128];      // [c][t]
    __shared__ float sB[16][132];      // [c][e] (padded)

    const int t0 = blockIdx.x * 128;
    const int e0 = blockIdx.y * 128;
    const int b  = blockIdx.z;
    const float* A = A_all + (size_t)b * CIN * T_;

    const int tid = threadIdx.x;
    const int tx = tid & 15;           // e direction
    const int ty = tid >> 4;           // t direction

    float acc[8][8];
    #pragma unroll
    for (int i = 0; i < 8; i++)
        #pragma unroll
        for (int j = 0; j < 8; j++) acc[i][j] = 0.f;

    float bia[8];
    #pragma unroll
    for (int j = 0; j < 8; j++) bia[j] = bias[e0 + tx * 8 + j];

    for (int c0 = 0; c0 < CIN; c0 += 16) {
        // Load A tile: 16 x 128 floats (coalesced along t)
        #pragma unroll
        for (int l = 0; l < 2; l++) {
            int idx = tid + l * 256;          // float4 index 0..511
            int kk = idx >> 5, t4 = idx & 31;
            float4 v = *reinterpret_cast<const float4*>(
                A + (size_t)(c0 + kk) * T_ + t0 + t4 * 4);
            *reinterpret_cast<float4*>(&sA[kk][t4 * 4]) = v;
        }
        // Load W tile transposed: read W[e][c] contiguous in c, store [c][e]
        #pragma unroll
        for (int l = 0; l < 2; l++) {
            int idx = tid + l * 256;
            int ee = idx >> 2, cq = idx & 3;
            float4 w = *reinterpret_cast<const float4*>(
                W + (size_t)(e0 + ee) * CIN + c0 + cq * 4);
            sB[cq * 4 + 0][ee] = w.x;
            sB[cq * 4 + 1][ee] = w.y;
            sB[cq * 4 + 2][ee] = w.z;
            sB[cq * 4 + 3][ee] = w.w;
        }
        __syncthreads();

        #pragma unroll
        for (int kk = 0; kk < 16; kk++) {
            float ra[8], rb[8];
            *reinterpret_cast<float4*>(&ra[0]) = *reinterpret_cast<float4*>(&sA[kk][ty * 8]);
            *reinterpret_cast<float4*>(&ra[4]) = *reinterpret_cast<float4*>(&sA[kk][ty * 8 + 4]);
            *reinterpret_cast<float4*>(&rb[0]) = *reinterpret_cast<float4*>(&sB[kk][tx * 8]);
            *reinterpret_cast<float4*>(&rb[4]) = *reinterpret_cast<float4*>(&sB[kk][tx * 8 + 4]);
            #pragma unroll
            for (int i = 0; i < 8; i++)
                #pragma unroll
                for (int j = 0; j < 8; j++) acc[i][j] += ra[i] * rb[j];
        }
        __syncthreads();
    }

    #pragma unroll
    for (int i = 0; i < 8; i++) {
        int n = b * T_ + t0 + ty * 8 + i;
        float* o = g_x + (size_t)n * E_ + e0 + tx * 8;
        float4 v0 = make_float4(acc[i][0] + bia[0], acc[i][1] + bia[1],
                                acc[i][2] + bia[2], acc[i][3] + bia[3]);
        float4 v1 = make_float4(acc[i][4] + bia[4], acc[i][5] + bia[5],
                                acc[i][6] + bia[6], acc[i][7] + bia[7]);
        *reinterpret_cast<float4*>(o)     = v0;
        *reinterpret_cast<float4*>(o + 4) = v1;
    }
}

// ---------------------------------------------------------------------------
// GEMM B + fused argmin: s[n][k] = x[n]·embed[k];  m = ||e_k||^2 - 2 s
// Packed (order-preserving float bits << 32 | k) -> atomicMin gives argmin
// with lowest-index tie-break, matching jnp.argmin.
// ---------------------------------------------------------------------------
__device__ __forceinline__ unsigned fl2ord(float f) {
    unsigned u = __float_as_uint(f);
    return (u & 0x80000000u) ? ~u : (u | 0x80000000u);
}

__global__ __launch_bounds__(256) void gemmB_k(const float* __restrict__ embed) {
    __shared__ float sX[16][132];      // [e][n]
    __shared__ float sE[16][132];      // [e][k]
    __shared__ unsigned long long sMin[128];

    const int n0 = blockIdx.x * 128;
    const int k0 = blockIdx.y * 128;
    const int tid = threadIdx.x;
    const int tx = tid & 15;           // k direction
    const int ty = tid >> 4;           // n direction

    if (tid < 128) sMin[tid] = 0xFFFFFFFFFFFFFFFFull;

    float acc[8][8];
    #pragma unroll
    for (int i = 0; i < 8; i++)
        #pragma unroll
        for (int j = 0; j < 8; j++) acc[i][j] = 0.f;

    for (int c0 = 0; c0 < E_; c0 += 16) {
        #pragma unroll
        for (int l = 0; l < 2; l++) {
            int idx = tid + l * 256;
            int rr = idx >> 2, cq = idx & 3;
            float4 v = *reinterpret_cast<const float4*>(
                g_x + (size_t)(n0 + rr) * E_ + c0 + cq * 4);
            sX[cq * 4 + 0][rr] = v.x;
            sX[cq * 4 + 1][rr] = v.y;
            sX[cq * 4 + 2][rr] = v.z;
            sX[cq * 4 + 3][rr] = v.w;
            float4 w = *reinterpret_cast<const float4*>(
                embed + (size_t)(k0 + rr) * E_ + c0 + cq * 4);
            sE[cq * 4 + 0][rr] = w.x;
            sE[cq * 4 + 1][rr] = w.y;
            sE[cq * 4 + 2][rr] = w.z;
            sE[cq * 4 + 3][rr] = w.w;
        }
        __syncthreads();

        #pragma unroll
        for (int kk = 0; kk < 16; kk++) {
            float ra[8], rb[8];
            *reinterpret_cast<float4*>(&ra[0]) = *reinterpret_cast<float4*>(&sX[kk][ty * 8]);
            *reinterpret_cast<float4*>(&ra[4]) = *reinterpret_cast<float4*>(&sX[kk][ty * 8 + 4]);
            *reinterpret_cast<float4*>(&rb[0]) = *reinterpret_cast<float4*>(&sE[kk][tx * 8]);
            *reinterpret_cast<float4*>(&rb[4]) = *reinterpret_cast<float4*>(&sE[kk][tx * 8 + 4]);
            #pragma unroll
            for (int i = 0; i < 8; i++)
                #pragma unroll
                for (int j = 0; j < 8; j++) acc[i][j] += ra[i] * rb[j];
        }
        __syncthreads();
    }

    float en[8];
    #pragma unroll
    for (int j = 0; j < 8; j++) en[j] = g_enorm[k0 + tx * 8 + j];

    #pragma unroll
    for (int i = 0; i < 8; i++) {
        unsigned long long best = 0xFFFFFFFFFFFFFFFFull;
        #pragma unroll
        for (int j = 0; j < 8; j++) {
            float m = en[j] - 2.0f * acc[i][j];
            unsigned long long p =
                ((unsigned long long)fl2ord(m) << 32) |
                (unsigned)(k0 + tx * 8 + j);
            best = (p < best) ? p : best;
        }
        atomicMin(&sMin[ty * 8 + i], best);
    }
    __syncthreads();
    if (tid < 128) atomicMin(&g_minpack[n0 + tid], sMin[tid]);
}

// ---------------------------------------------------------------------------
// Gather + transpose write + loss partials + histogram
// 32 tokens per block, 256 threads.
// ---------------------------------------------------------------------------
__global__ __launch_bounds__(256) void gather_k(const float* __restrict__ embed,
                                                float* __restrict__ out) {
    __shared__ float zq[32][257];
    __shared__ int   kidx[32];
    __shared__ float wsum[8];

    const int n0 = blockIdx.x * 32;
    const int b  = n0 >> 12;           // /4096
    const int t0 = n0 & 4095;
    const int tid = threadIdx.x;

    if (tid < 32) {
        unsigned long long mp = g_minpack[n0 + tid];
        int k = (int)(unsigned)(mp & 0xFFFFFFFFull);
        kidx[tid] = k;
        atomicAdd(&g_count[k], 1);
    }
    __syncthreads();

    float accl = 0.f;
    for (int idx = tid; idx < 32 * E_; idx += 256) {
        int t = idx >> 8, e = idx & 255;
        float v = embed[(size_t)kidx[t] * E_ + e];
        zq[t][e] = v;
        float d = v - g_x[(size_t)(n0 + t) * E_ + e];
        accl += d * d;
    }
    __syncthreads();

    // transpose write: out[b][e][t], coalesced along t
    for (int idx = tid; idx < 32 * E_; idx += 256) {
        int e = idx >> 5, t = idx & 31;
        out[(size_t)b * E_ * T_ + (size_t)e * T_ + t0 + t] = zq[t][e];
    }

    #pragma unroll
    for (int o = 16; o; o >>= 1) accl += __shfl_down_sync(0xffffffffu, accl, o);
    if ((tid & 31) == 0) wsum[tid >> 5] = accl;
    __syncthreads();
    if (tid == 0) {
        float s = 0.f;
        #pragma unroll
        for (int w = 0; w < 8; w++) s += wsum[w];
        g_losspart[blockIdx.x] = s;
    }
}

// ---------------------------------------------------------------------------
// Final scalars: loss, kldiv (constant), log-perplexity
// ---------------------------------------------------------------------------
__global__ void final_k(float* __restrict__ out, int out_size) {
    __shared__ float red[256];
    const int tid = threadIdx.x;

    float s = 0.f;
    for (int i = tid; i < NGATH; i += 256) s += g_losspart[i];
    red[tid] = s;
    __syncthreads();
    #pragma unroll
    for (int o = 128; o; o >>= 1) {
        if (tid < o) red[tid] += red[tid + o];
        __syncthreads();
    }
    float loss = red[0] * (1.25f / (float)((size_t)NTOK * E_));
    __syncthreads();

    float pl = 0.f;
    for (int k = tid; k < NC; k += 256) {
        float p = (float)g_count[k] * (1.0f / (float)NTOK);
        pl += p * logf(p + 1e-10f);
    }
    red[tid] = pl;
    __syncthreads();
    #pragma unroll
    for (int o = 128; o; o >>= 1) {
        if (tid < o) red[tid] += red[tid + o];
        __syncthreads();
    }
    float logperp = -red[0];

    if (tid == 0) {
        const float kconst = (float)(log(1024.0) * 4096.0);
        long long base = (long long)NTOK * E_;   // 16777216
        if (base < (long long)out_size) out[base] = loss;
        for (int i = 0; i < B_; i++)
            if (base + 1 + i < (long long)out_size) out[base + 1 + i] = kconst;
        if (base + 1 + B_ < (long long)out_size) out[base + 1 + B_] = logperp;
    }
}

// ---------------------------------------------------------------------------
// Launch
// ---------------------------------------------------------------------------
extern "C" void kernel_launch(void* const* d_in, const int* in_sizes, int n_in,
                              void* d_out, int out_size) {
    const float* inputs = (const float*)d_in[0];   // [16, 512, 4096]
    const float* proj_w = (const float*)d_in[1];   // [256, 512]
    const float* proj_b = (const float*)d_in[2];   // [256]
    const float* embed  = (const float*)d_in[3];   // [1024, 256]
    float* out = (float*)d_out;

    init_k<<<256, 256>>>();
    enorm_k<<<128, 256>>>(embed);

    dim3 gA(T_ / 128, E_ / 128, B_);               // 32 x 2 x 16
    gemmA_k<<<gA, 256>>>(inputs, proj_w, proj_b);

    dim3 gB(NTOK / 128, NC / 128);                 // 512 x 8
    gemmB_k<<<gB, 256>>>(embed);

    gather_k<<<NGATH, 256>>>(embed, out);
    final_k<<<1, 256>>>(out, out_size);
}